// round 2
// baseline (speedup 1.0000x reference)
#include <cuda_runtime.h>

// Problem dims (fixed by the reference)
constexpr int B_  = 8;
constexpr int T_  = 2048;
constexpr int D_  = 1024;
constexpr int DO_ = 1024;
constexpr int MROWS = B_ * T_;   // 16384

// Scratch (no cudaMalloc allowed): q/k/v 64 MB each, scores 128 MB.
__device__ float g_q[(size_t)MROWS * D_];
__device__ float g_k[(size_t)MROWS * D_];
__device__ float g_v[(size_t)MROWS * DO_];
__device__ float g_s[(size_t)B_ * T_ * T_];

// ---------------------------------------------------------------------------
// 128x128x8 SGEMM tile, 256 threads, 8x8 per thread (split 4+4 halves for
// conflict-free smem fragment loads). C = alpha * A @ B(^T) [+ bias].
// A: [M,K] row-major. B: NN -> [K,N] row-major; NT -> [N,K] row-major.
// All of M, N divisible by 128, K divisible by 8. ldC == N.
// ---------------------------------------------------------------------------
template<bool TRANS_B, bool HAS_BIAS>
__device__ __forceinline__ void gemm128(
    const float* __restrict__ A, const float* __restrict__ Bm,
    float* __restrict__ C, const float* __restrict__ bias,
    int N, int K, float alpha, int bm, int bn)
{
    __shared__ float As[8][128];
    __shared__ float Bs[8][128];

    const int tid = threadIdx.x;
    const int tx  = tid & 15;     // 0..15
    const int ty  = tid >> 4;     // 0..15

    // global-load mapping
    const int arow = tid >> 1;           // 0..127
    const int acol = (tid & 1) << 2;     // 0 or 4
    const int brow = tid >> 5;           // 0..7   (NN)
    const int bcol = (tid & 31) << 2;    // 0..124 (NN)

    float acc[8][8];
#pragma unroll
    for (int i = 0; i < 8; i++)
#pragma unroll
        for (int j = 0; j < 8; j++) acc[i][j] = 0.0f;

    for (int k0 = 0; k0 < K; k0 += 8) {
        // A tile: 128 rows x 8 k, stored transposed As[k][m]
        float4 av = *(const float4*)&A[(size_t)(bm + arow) * K + (k0 + acol)];
        As[acol + 0][arow] = av.x;
        As[acol + 1][arow] = av.y;
        As[acol + 2][arow] = av.z;
        As[acol + 3][arow] = av.w;

        if (TRANS_B) {
            // B is [N,K]: load rows bn..bn+127 of B, k-slice, store Bs[k][n]
            float4 bv = *(const float4*)&Bm[(size_t)(bn + arow) * K + (k0 + acol)];
            Bs[acol + 0][arow] = bv.x;
            Bs[acol + 1][arow] = bv.y;
            Bs[acol + 2][arow] = bv.z;
            Bs[acol + 3][arow] = bv.w;
        } else {
            // B is [K,N]: rows k0..k0+7, cols bn..bn+127 (contiguous)
            float4 bv = *(const float4*)&Bm[(size_t)(k0 + brow) * N + (bn + bcol)];
            *(float4*)&Bs[brow][bcol] = bv;
        }
        __syncthreads();

#pragma unroll
        for (int kk = 0; kk < 8; kk++) {
            float a[8], b[8];
            *(float4*)&a[0] = *(const float4*)&As[kk][ty * 4];
            *(float4*)&a[4] = *(const float4*)&As[kk][64 + ty * 4];
            *(float4*)&b[0] = *(const float4*)&Bs[kk][tx * 4];
            *(float4*)&b[4] = *(const float4*)&Bs[kk][64 + tx * 4];
#pragma unroll
            for (int i = 0; i < 8; i++)
#pragma unroll
                for (int j = 0; j < 8; j++)
                    acc[i][j] = fmaf(a[i], b[j], acc[i][j]);
        }
        __syncthreads();
    }

    // epilogue: rows {ty*4+i, 64+ty*4+i}, cols {tx*4+j, 64+tx*4+j}
#pragma unroll
    for (int i = 0; i < 8; i++) {
        const int row = bm + ((i < 4) ? (ty * 4 + i) : (64 + ty * 4 + (i - 4)));
#pragma unroll
        for (int h = 0; h < 2; h++) {
            const int col = bn + (h == 0 ? tx * 4 : 64 + tx * 4);
            const int j0  = h * 4;
            float4 o;
            o.x = acc[i][j0 + 0] * alpha;
            o.y = acc[i][j0 + 1] * alpha;
            o.z = acc[i][j0 + 2] * alpha;
            o.w = acc[i][j0 + 3] * alpha;
            if (HAS_BIAS) {
                o.x += bias[col + 0];
                o.y += bias[col + 1];
                o.z += bias[col + 2];
                o.w += bias[col + 3];
            }
            *(float4*)&C[(size_t)row * N + col] = o;
        }
    }
}

// ---------------------------------------------------------------------------
// Kernel 1: q/k/v = X @ W{q,k,v} + b{q,k,v}   (blockIdx.z selects projection)
// ---------------------------------------------------------------------------
__global__ __launch_bounds__(256, 2) void qkv_kernel(
    const float* __restrict__ X,
    const float* __restrict__ W0, const float* __restrict__ b0,
    const float* __restrict__ W1, const float* __restrict__ b1,
    const float* __restrict__ W2, const float* __restrict__ b2)
{
    const float* W; const float* bias; float* C;
    if (blockIdx.z == 0)      { W = W0; bias = b0; C = g_q; }
    else if (blockIdx.z == 1) { W = W1; bias = b1; C = g_k; }
    else                      { W = W2; bias = b2; C = g_v; }
    gemm128<false, true>(X, W, C, bias, D_, D_, 1.0f,
                         blockIdx.y * 128, blockIdx.x * 128);
}

// ---------------------------------------------------------------------------
// Kernel 2: S[b] = (Q[b] @ K[b]^T) / sqrt(D)   (NT GEMM per batch)
// ---------------------------------------------------------------------------
__global__ __launch_bounds__(256, 2) void scores_kernel()
{
    const int b = blockIdx.z;
    gemm128<true, false>(g_q + (size_t)b * T_ * D_,
                         g_k + (size_t)b * T_ * D_,
                         g_s + (size_t)b * T_ * T_, nullptr,
                         T_, D_, 0.03125f,   // 1/sqrt(1024)
                         blockIdx.y * 128, blockIdx.x * 128);
}

// ---------------------------------------------------------------------------
// Kernel 3: row-wise softmax over S (rows of length T_=2048), in place.
// One block of 256 threads per row, 8 elems per thread.
// ---------------------------------------------------------------------------
__global__ __launch_bounds__(256) void softmax_kernel()
{
    __shared__ float sh[8];
    float* row = g_s + (size_t)blockIdx.x * T_;
    const int tid = threadIdx.x;

    float x[8];
    float4 v0 = ((const float4*)row)[tid * 2 + 0];
    float4 v1 = ((const float4*)row)[tid * 2 + 1];
    x[0] = v0.x; x[1] = v0.y; x[2] = v0.z; x[3] = v0.w;
    x[4] = v1.x; x[5] = v1.y; x[6] = v1.z; x[7] = v1.w;

    // --- max reduce ---
    float m = x[0];
#pragma unroll
    for (int i = 1; i < 8; i++) m = fmaxf(m, x[i]);
#pragma unroll
    for (int o = 16; o > 0; o >>= 1) m = fmaxf(m, __shfl_xor_sync(0xffffffffu, m, o));
    if ((tid & 31) == 0) sh[tid >> 5] = m;
    __syncthreads();
    if (tid < 32) {
        float t = (tid < 8) ? sh[tid] : -3.0e38f;
#pragma unroll
        for (int o = 4; o > 0; o >>= 1) t = fmaxf(t, __shfl_xor_sync(0xffffffffu, t, o));
        if (tid == 0) sh[0] = t;
    }
    __syncthreads();
    m = sh[0];
    __syncthreads();

    // --- exp + sum reduce ---
    float s = 0.0f;
#pragma unroll
    for (int i = 0; i < 8; i++) { x[i] = expf(x[i] - m); s += x[i]; }
#pragma unroll
    for (int o = 16; o > 0; o >>= 1) s += __shfl_xor_sync(0xffffffffu, s, o);
    if ((tid & 31) == 0) sh[tid >> 5] = s;
    __syncthreads();
    if (tid < 32) {
        float t = (tid < 8) ? sh[tid] : 0.0f;
#pragma unroll
        for (int o = 4; o > 0; o >>= 1) t += __shfl_xor_sync(0xffffffffu, t, o);
        if (tid == 0) sh[0] = t;
    }
    __syncthreads();
    const float inv = 1.0f / sh[0];

    v0.x = x[0] * inv; v0.y = x[1] * inv; v0.z = x[2] * inv; v0.w = x[3] * inv;
    v1.x = x[4] * inv; v1.y = x[5] * inv; v1.z = x[6] * inv; v1.w = x[7] * inv;
    ((float4*)row)[tid * 2 + 0] = v0;
    ((float4*)row)[tid * 2 + 1] = v1;
}

// ---------------------------------------------------------------------------
// Kernel 4: O[b] = P[b] @ V[b]   (NN GEMM per batch) -> d_out
// ---------------------------------------------------------------------------
__global__ __launch_bounds__(256, 2) void pv_kernel(float* __restrict__ out)
{
    const int b = blockIdx.z;
    gemm128<false, false>(g_s + (size_t)b * T_ * T_,
                          g_v + (size_t)b * T_ * DO_,
                          out + (size_t)b * T_ * DO_, nullptr,
                          DO_, T_, 1.0f,
                          blockIdx.y * 128, blockIdx.x * 128);
}

// ---------------------------------------------------------------------------
extern "C" void kernel_launch(void* const* d_in, const int* in_sizes, int n_in,
                              void* d_out, int out_size)
{
    const float* X  = (const float*)d_in[0];
    const float* Wq = (const float*)d_in[1];
    const float* bq = (const float*)d_in[2];
    const float* Wk = (const float*)d_in[3];
    const float* bk = (const float*)d_in[4];
    const float* Wv = (const float*)d_in[5];
    const float* bv = (const float*)d_in[6];
    float* out = (float*)d_out;

    dim3 thr(256);
    qkv_kernel<<<dim3(D_ / 128, MROWS / 128, 3), thr>>>(X, Wq, bq, Wk, bk, Wv, bv);
    scores_kernel<<<dim3(T_ / 128, T_ / 128, B_), thr>>>();
    softmax_kernel<<<dim3(B_ * T_), thr>>>();
    pv_kernel<<<dim3(DO_ / 128, T_ / 128, B_), thr>>>(out);
}

// round 13
// speedup vs baseline: 2.0291x; 2.0291x over previous
#include <cuda_runtime.h>
#include <cuda_bf16.h>
#include <cstdint>

using bf16 = __nv_bfloat16;

constexpr int Bz = 8, T_ = 2048, D_ = 1024, DOv = 1024, Mr = 16384; // Mr = Bz*T_

// ---------------- scratch (no cudaMalloc allowed) ----------------
__device__ bf16  g_xhi[(size_t)Mr * D_],  g_xlo[(size_t)Mr * D_];
__device__ bf16  g_wthi[(size_t)3 * D_ * D_], g_wtlo[(size_t)3 * D_ * D_];
__device__ bf16  g_qhi[(size_t)Mr * D_],  g_qlo[(size_t)Mr * D_];
__device__ bf16  g_khi[(size_t)Mr * D_],  g_klo[(size_t)Mr * D_];
__device__ float g_v[(size_t)Mr * DOv];
__device__ bf16  g_vthi[(size_t)Bz * DOv * T_], g_vtlo[(size_t)Bz * DOv * T_];
__device__ float g_s[(size_t)Bz * T_ * T_];
__device__ bf16  g_phi[(size_t)Bz * T_ * T_], g_plo[(size_t)Bz * T_ * T_];

// ---------------- portable (compute_80+) asm helpers ----------------
#define CP_ASYNC16(dst, src) \
    asm volatile("cp.async.cg.shared.global [%0], [%1], 16;" :: "r"(dst), "l"(src))
#define CP_COMMIT() asm volatile("cp.async.commit_group;" ::: "memory")
#define CP_WAIT(N)  asm volatile("cp.async.wait_group %0;" :: "n"(N) : "memory")

#define LDSM4(r, a) \
    asm volatile("ldmatrix.sync.aligned.m8n8.x4.shared.b16 {%0,%1,%2,%3}, [%4];" \
                 : "=r"((r)[0]), "=r"((r)[1]), "=r"((r)[2]), "=r"((r)[3]) : "r"(a))
#define LDSM2(r, a) \
    asm volatile("ldmatrix.sync.aligned.m8n8.x2.shared.b16 {%0,%1}, [%2];" \
                 : "=r"((r)[0]), "=r"((r)[1]) : "r"(a))

#define MMA16816(d, a, b) \
    asm volatile("mma.sync.aligned.m16n8k16.row.col.f32.bf16.bf16.f32 " \
                 "{%0,%1,%2,%3}, {%4,%5,%6,%7}, {%8,%9}, {%0,%1,%2,%3};" \
                 : "+f"((d)[0]), "+f"((d)[1]), "+f"((d)[2]), "+f"((d)[3]) \
                 : "r"((a)[0]), "r"((a)[1]), "r"((a)[2]), "r"((a)[3]), \
                   "r"((b)[0]), "r"((b)[1]))

// ---------------- HMMA split-bf16 GEMM: C = alpha*(A @ B^T) [+bias] ----------------
// A: [M,K] K-major split (hi/lo). B: [N,K] K-major split.
// CTA tile 128x128, Kchunk=32, 8 warps (2x4), warp tile 64x32.
// smem row = 32 bf16 (64B) padded to 80B -> conflict-free ldmatrix (r*80 walks all banks).
constexpr int BM = 128, BN = 128, BK = 32;
constexpr int ROWB   = 80;            // bytes per smem row
constexpr int TILEB  = 128 * ROWB;    // 10240 B per tile
constexpr int STAGEB = 4 * TILEB;     // Ahi,Alo,Bhi,Blo
constexpr int SMEMB  = 2 * STAGEB;    // 81920 B double-buffered

template<bool SPLIT>
__global__ __launch_bounds__(256, 1) void mma_gemm(
    const bf16* __restrict__ Ahi, const bf16* __restrict__ Alo,
    const bf16* __restrict__ Bhi, const bf16* __restrict__ Blo,
    int ldA, int ldB, int K,
    long long sA, long long sB, long long sC,
    float* __restrict__ Cf, bf16* __restrict__ Chi, bf16* __restrict__ Clo,
    const float* __restrict__ bias, float alpha, int ldC)
{
    extern __shared__ char smem[];
    const uint32_t sb = (uint32_t)__cvta_generic_to_shared(smem);
    const int tid = threadIdx.x, wid = tid >> 5, lane = tid & 31;
    const int bm = blockIdx.y * BM, bn = blockIdx.x * BN;
    const long long z = blockIdx.z;

    Ahi += z * sA; Alo += z * sA;
    Bhi += z * sB; Blo += z * sB;
    if (SPLIT) { Chi += z * sC; Clo += z * sC; } else { Cf += z * sC; }

    const int warp_m = wid >> 2, warp_n = wid & 3;   // 2 x 4

    float acc[4][4][4];
#pragma unroll
    for (int mi = 0; mi < 4; ++mi)
#pragma unroll
        for (int ni = 0; ni < 4; ++ni)
#pragma unroll
            for (int r = 0; r < 4; ++r) acc[mi][ni][r] = 0.0f;

    const bf16* srcs[4] = {Ahi, Alo, Bhi, Blo};
    const int   rowofs[4] = {bm, bm, bn, bn};
    const int   lds[4]    = {ldA, ldA, ldB, ldB};

    const int nchunk = K / BK;

    // ---- async stage loader: 4 tiles x 128 rows x 4 16B segments ----
    auto issue_stage = [&](int it, int buf) {
        const int k0 = it * BK;
        const uint32_t dst0 = sb + buf * STAGEB;
#pragma unroll
        for (int t = 0; t < 4; ++t) {
            const bf16* base = srcs[t];
            const int ro = rowofs[t], ld = lds[t];
#pragma unroll
            for (int j = 0; j < 2; ++j) {
                const int i = tid + j * 256;          // 0..511
                const int r = i >> 2, seg = i & 3;
                const bf16* src = base + (size_t)(ro + r) * ld + k0 + seg * 8;
                const uint32_t dst = dst0 + t * TILEB + r * ROWB + seg * 16;
                CP_ASYNC16(dst, src);
            }
        }
        CP_COMMIT();
    };

    issue_stage(0, 0);

    for (int it = 0; it < nchunk; ++it) {
        if (it + 1 < nchunk) { issue_stage(it + 1, (it + 1) & 1); CP_WAIT(1); }
        else                 { CP_WAIT(0); }
        __syncthreads();

        const uint32_t sbuf = sb + (it & 1) * STAGEB;
        const int lr = lane & 15, lc = lane >> 4;          // A ldmatrix addr
        const int br = lane & 7,  bc = (lane >> 3) & 1;    // B ldmatrix addr

#pragma unroll
        for (int ks = 0; ks < 2; ++ks) {
            const int k = ks * 16;
            uint32_t ah[4][4], al[4][4];
#pragma unroll
            for (int mi = 0; mi < 4; ++mi) {
                const uint32_t a = sbuf + (warp_m * 64 + mi * 16 + lr) * ROWB
                                 + (k + lc * 8) * 2;
                LDSM4(ah[mi], a);
                LDSM4(al[mi], a + TILEB);
            }
            uint32_t bh[4][2], bl[4][2];
#pragma unroll
            for (int ni = 0; ni < 4; ++ni) {
                const uint32_t a = sbuf + 2 * TILEB
                                 + (warp_n * 32 + ni * 8 + br) * ROWB
                                 + (k + bc * 8) * 2;
                LDSM2(bh[ni], a);
                LDSM2(bl[ni], a + TILEB);
            }
#pragma unroll
            for (int mi = 0; mi < 4; ++mi)
#pragma unroll
                for (int ni = 0; ni < 4; ++ni) {
                    MMA16816(acc[mi][ni], ah[mi], bh[ni]);   // hi*hi
                    MMA16816(acc[mi][ni], ah[mi], bl[ni]);   // hi*lo
                    MMA16816(acc[mi][ni], al[mi], bh[ni]);   // lo*hi
                }
        }
        __syncthreads();
    }

    // ---- epilogue: fragment layout -> direct global stores ----
    const int r0 = bm + warp_m * 64;
    const int c0 = bn + warp_n * 32;
    const int lr4 = lane >> 2, lc2 = (lane & 3) * 2;
#pragma unroll
    for (int ni = 0; ni < 4; ++ni) {
        const int col = c0 + ni * 8 + lc2;
        const float b0 = bias ? bias[col]     : 0.0f;
        const float b1 = bias ? bias[col + 1] : 0.0f;
#pragma unroll
        for (int mi = 0; mi < 4; ++mi) {
            const int row1 = r0 + mi * 16 + lr4;
            const int row2 = row1 + 8;
#pragma unroll
            for (int h = 0; h < 2; ++h) {
                const int row = (h == 0) ? row1 : row2;
                const float v0 = fmaf(acc[mi][ni][h * 2 + 0], alpha, b0);
                const float v1 = fmaf(acc[mi][ni][h * 2 + 1], alpha, b1);
                const size_t o = (size_t)row * ldC + col;
                if (SPLIT) {
                    const bf16 h0 = __float2bfloat16(v0);
                    const bf16 h1 = __float2bfloat16(v1);
                    __nv_bfloat162 hv; hv.x = h0; hv.y = h1;
                    __nv_bfloat162 lv;
                    lv.x = __float2bfloat16(v0 - __bfloat162float(h0));
                    lv.y = __float2bfloat16(v1 - __bfloat162float(h1));
                    *reinterpret_cast<__nv_bfloat162*>(Chi + o) = hv;
                    *reinterpret_cast<__nv_bfloat162*>(Clo + o) = lv;
                } else {
                    float2 fv; fv.x = v0; fv.y = v1;
                    *reinterpret_cast<float2*>(Cf + o) = fv;
                }
            }
        }
    }
}

// ---------------- aux kernels ----------------
__global__ __launch_bounds__(256) void split_x_kernel(const float* __restrict__ src,
                                                      bf16* __restrict__ hi, bf16* __restrict__ lo)
{
    const size_t i = (size_t)blockIdx.x * 256 + threadIdx.x;   // over float4s
    const float4 v = reinterpret_cast<const float4*>(src)[i];
    float vs[4] = {v.x, v.y, v.z, v.w};
    __nv_bfloat162 h2[2], l2[2];
#pragma unroll
    for (int j = 0; j < 4; ++j) {
        bf16 h = __float2bfloat16(vs[j]);
        bf16 l = __float2bfloat16(vs[j] - __bfloat162float(h));
        ((bf16*)h2)[j] = h; ((bf16*)l2)[j] = l;
    }
    reinterpret_cast<__nv_bfloat162*>(hi)[i * 2 + 0] = h2[0];
    reinterpret_cast<__nv_bfloat162*>(hi)[i * 2 + 1] = h2[1];
    reinterpret_cast<__nv_bfloat162*>(lo)[i * 2 + 0] = l2[0];
    reinterpret_cast<__nv_bfloat162*>(lo)[i * 2 + 1] = l2[1];
}

// dst[c][r] = split(src[r][c]); src [R,C] row-major, dst [C,R]
__global__ __launch_bounds__(256) void tsplit_kernel(const float* __restrict__ src,
                                                     bf16* __restrict__ dhi, bf16* __restrict__ dlo,
                                                     int R, int C, long long sSrc, long long sDst)
{
    __shared__ float t[32][33];
    const float* s = src + (long long)blockIdx.z * sSrc;
    bf16* dh = dhi + (long long)blockIdx.z * sDst;
    bf16* dl = dlo + (long long)blockIdx.z * sDst;
    const int x0 = blockIdx.x * 32, y0 = blockIdx.y * 32;
    const int tx = threadIdx.x & 31, ty = threadIdx.x >> 5;   // (32,8)
#pragma unroll
    for (int j = 0; j < 4; ++j)
        t[ty + 8 * j][tx] = s[(size_t)(y0 + ty + 8 * j) * C + x0 + tx];
    __syncthreads();
#pragma unroll
    for (int j = 0; j < 4; ++j) {
        const float v = t[tx][ty + 8 * j];
        const bf16 h = __float2bfloat16(v);
        const size_t o = (size_t)(x0 + ty + 8 * j) * R + y0 + tx;
        dh[o] = h;
        dl[o] = __float2bfloat16(v - __bfloat162float(h));
    }
}

__global__ __launch_bounds__(256) void softmax_split_kernel()
{
    __shared__ float sh[8];
    const float* row = g_s + (size_t)blockIdx.x * T_;
    bf16* ph = g_phi + (size_t)blockIdx.x * T_;
    bf16* pl = g_plo + (size_t)blockIdx.x * T_;
    const int tid = threadIdx.x;

    float x[8];
    float4 v0 = reinterpret_cast<const float4*>(row)[tid * 2 + 0];
    float4 v1 = reinterpret_cast<const float4*>(row)[tid * 2 + 1];
    x[0]=v0.x; x[1]=v0.y; x[2]=v0.z; x[3]=v0.w;
    x[4]=v1.x; x[5]=v1.y; x[6]=v1.z; x[7]=v1.w;

    float m = x[0];
#pragma unroll
    for (int i = 1; i < 8; ++i) m = fmaxf(m, x[i]);
#pragma unroll
    for (int o = 16; o > 0; o >>= 1) m = fmaxf(m, __shfl_xor_sync(0xffffffffu, m, o));
    if ((tid & 31) == 0) sh[tid >> 5] = m;
    __syncthreads();
    if (tid < 32) {
        float t = (tid < 8) ? sh[tid] : -3.0e38f;
#pragma unroll
        for (int o = 4; o > 0; o >>= 1) t = fmaxf(t, __shfl_xor_sync(0xffffffffu, t, o));
        if (tid == 0) sh[0] = t;
    }
    __syncthreads();
    m = sh[0];
    __syncthreads();

    float s = 0.0f;
#pragma unroll
    for (int i = 0; i < 8; ++i) { x[i] = expf(x[i] - m); s += x[i]; }
#pragma unroll
    for (int o = 16; o > 0; o >>= 1) s += __shfl_xor_sync(0xffffffffu, s, o);
    if ((tid & 31) == 0) sh[tid >> 5] = s;
    __syncthreads();
    if (tid < 32) {
        float t = (tid < 8) ? sh[tid] : 0.0f;
#pragma unroll
        for (int o = 4; o > 0; o >>= 1) t += __shfl_xor_sync(0xffffffffu, t, o);
        if (tid == 0) sh[0] = t;
    }
    __syncthreads();
    const float inv = 1.0f / sh[0];

#pragma unroll
    for (int j = 0; j < 8; ++j) {
        const float p = x[j] * inv;
        const bf16 h = __float2bfloat16(p);
        ph[tid * 8 + j] = h;
        pl[tid * 8 + j] = __float2bfloat16(p - __bfloat162float(h));
    }
}

// ---------------- launch ----------------
extern "C" void kernel_launch(void* const* d_in, const int* in_sizes, int n_in,
                              void* d_out, int out_size)
{
    const float* X  = (const float*)d_in[0];
    const float* Wq = (const float*)d_in[1];
    const float* bq = (const float*)d_in[2];
    const float* Wk = (const float*)d_in[3];
    const float* bk = (const float*)d_in[4];
    const float* Wv = (const float*)d_in[5];
    const float* bv = (const float*)d_in[6];
    float* out = (float*)d_out;

    cudaFuncSetAttribute(mma_gemm<true>,  cudaFuncAttributeMaxDynamicSharedMemorySize, SMEMB);
    cudaFuncSetAttribute(mma_gemm<false>, cudaFuncAttributeMaxDynamicSharedMemorySize, SMEMB);

    bf16 *xhi, *xlo, *wthi, *wtlo, *qhi, *qlo, *khi, *klo, *vthi, *vtlo, *phi, *plo;
    float *vv, *ss;
    cudaGetSymbolAddress((void**)&xhi, g_xhi);   cudaGetSymbolAddress((void**)&xlo, g_xlo);
    cudaGetSymbolAddress((void**)&wthi, g_wthi); cudaGetSymbolAddress((void**)&wtlo, g_wtlo);
    cudaGetSymbolAddress((void**)&qhi, g_qhi);   cudaGetSymbolAddress((void**)&qlo, g_qlo);
    cudaGetSymbolAddress((void**)&khi, g_khi);   cudaGetSymbolAddress((void**)&klo, g_klo);
    cudaGetSymbolAddress((void**)&vv, g_v);
    cudaGetSymbolAddress((void**)&vthi, g_vthi); cudaGetSymbolAddress((void**)&vtlo, g_vtlo);
    cudaGetSymbolAddress((void**)&ss, g_s);
    cudaGetSymbolAddress((void**)&phi, g_phi);   cudaGetSymbolAddress((void**)&plo, g_plo);

    const dim3 thr(256);

    // 1) split X
    split_x_kernel<<<(unsigned)((size_t)Mr * D_ / 4 / 256), thr>>>(X, xhi, xlo);

    // 2) transpose+split W^T (dst [N,K])
    tsplit_kernel<<<dim3(32, 32, 1), thr>>>(Wq, wthi,                       wtlo,                       D_, D_, 0, 0);
    tsplit_kernel<<<dim3(32, 32, 1), thr>>>(Wk, wthi + (size_t)D_ * D_,     wtlo + (size_t)D_ * D_,     D_, D_, 0, 0);
    tsplit_kernel<<<dim3(32, 32, 1), thr>>>(Wv, wthi + (size_t)2 * D_ * D_, wtlo + (size_t)2 * D_ * D_, D_, D_, 0, 0);

    // 3) QKV projections (HMMA, 3-term split)
    mma_gemm<true><<<dim3(D_/BN, Mr/BM, 1), thr, SMEMB>>>(
        xhi, xlo, wthi, wtlo, D_, D_, D_, 0, 0, 0,
        nullptr, qhi, qlo, bq, 1.0f, D_);
    mma_gemm<true><<<dim3(D_/BN, Mr/BM, 1), thr, SMEMB>>>(
        xhi, xlo, wthi + (size_t)D_ * D_, wtlo + (size_t)D_ * D_, D_, D_, D_, 0, 0, 0,
        nullptr, khi, klo, bk, 1.0f, D_);
    mma_gemm<false><<<dim3(DOv/BN, Mr/BM, 1), thr, SMEMB>>>(
        xhi, xlo, wthi + (size_t)2 * D_ * D_, wtlo + (size_t)2 * D_ * D_, D_, D_, D_, 0, 0, 0,
        vv, nullptr, nullptr, bv, 1.0f, DOv);

    // 4) V^T split per batch: [T,DO] -> [DO,T]
    tsplit_kernel<<<dim3(DOv/32, T_/32, Bz), thr>>>(vv, vthi, vtlo, T_, DOv,
                                                    (long long)T_ * DOv, (long long)DOv * T_);

    // 5) scores = (Q K^T)/32, fp32
    mma_gemm<false><<<dim3(T_/BN, T_/BM, Bz), thr, SMEMB>>>(
        qhi, qlo, khi, klo, D_, D_, D_,
        (long long)T_ * D_, (long long)T_ * D_, (long long)T_ * T_,
        ss, nullptr, nullptr, nullptr, 0.03125f, T_);

    // 6) softmax -> P split
    softmax_split_kernel<<<Bz * T_, thr>>>();

    // 7) out = P V
    mma_gemm<false><<<dim3(DOv/BN, T_/BM, Bz), thr, SMEMB>>>(
        phi, plo, vthi, vtlo, T_, T_, T_,
        (long long)T_ * T_, (long long)DOv * T_, (long long)T_ * DOv,
        out, nullptr, nullptr, nullptr, 1.0f, DOv);
}